// round 13
// baseline (speedup 1.0000x reference)
#include <cuda_runtime.h>
#include <cuda_bf16.h>
#include <cuda_fp16.h>
#include <math.h>
#include <stdint.h>

#define B_    16
#define C_    256
#define N_    4096
#define HEADS 8
#define DH    32
#define QKV3  768
#define LN_EPS 1e-5f
#define L2_EPS 1e-12f
#define XC_SCALE 8.0f
#define ZSPLIT 8

// ---------------- scratch ----------------
__device__ __nv_bfloat16 g_thi[(size_t)B_ * N_ * C_];
__device__ __nv_bfloat16 g_tlo[(size_t)B_ * N_ * C_];
__device__ float g_qkv[(size_t)B_ * QKV3 * N_];
__device__ float g_norm2[B_ * 512];
__device__ float g_simpart[ZSPLIT * B_ * HEADS * DH * DH];
__device__ float g_attn[B_ * HEADS * DH * DH];
__device__ __half g_mhi[(size_t)B_ * C_ * C_];            // M = Wout^T ∘ attn, [b][o][c]
__device__ __half g_mlo[(size_t)B_ * C_ * C_];
__device__ __nv_bfloat16 g_wqh[QKV3 * C_];
__device__ __nv_bfloat16 g_wql[QKV3 * C_];

__device__ __forceinline__ uint32_t smem_u32(const void* p) {
    uint32_t a;
    asm("{ .reg .u64 t; cvta.to.shared.u64 t, %1; cvt.u32.u64 %0, t; }" : "=r"(a) : "l"(p));
    return a;
}
__device__ __forceinline__ void mma_bf16(float* c, const uint32_t* a, const uint32_t* b) {
    asm volatile("mma.sync.aligned.m16n8k16.row.col.f32.bf16.bf16.f32 "
                 "{%0,%1,%2,%3}, {%4,%5,%6,%7}, {%8,%9}, {%0,%1,%2,%3};"
                 : "+f"(c[0]), "+f"(c[1]), "+f"(c[2]), "+f"(c[3])
                 : "r"(a[0]), "r"(a[1]), "r"(a[2]), "r"(a[3]), "r"(b[0]), "r"(b[1]));
}
__device__ __forceinline__ void mma_f16(float* c, const uint32_t* a, const uint32_t* b) {
    asm volatile("mma.sync.aligned.m16n8k16.row.col.f32.f16.f16.f32 "
                 "{%0,%1,%2,%3}, {%4,%5,%6,%7}, {%8,%9}, {%0,%1,%2,%3};"
                 : "+f"(c[0]), "+f"(c[1]), "+f"(c[2]), "+f"(c[3])
                 : "r"(a[0]), "r"(a[1]), "r"(a[2]), "r"(a[3]), "r"(b[0]), "r"(b[1]));
}
__device__ __forceinline__ void ldsm4(uint32_t* r, uint32_t addr) {
    asm volatile("ldmatrix.sync.aligned.m8n8.x4.shared.b16 {%0,%1,%2,%3}, [%4];"
                 : "=r"(r[0]), "=r"(r[1]), "=r"(r[2]), "=r"(r[3]) : "r"(addr));
}
__device__ __forceinline__ void cp16(uint32_t sa, const void* ga) {
    asm volatile("cp.async.cg.shared.global [%0], [%1], 16;" :: "r"(sa), "l"(ga) : "memory");
}
#define CP_COMMIT() asm volatile("cp.async.commit_group;" ::: "memory")
#define CP_WAIT1()  asm volatile("cp.async.wait_group 1;" ::: "memory")
#define CP_WAIT0()  asm volatile("cp.async.wait_group 0;" ::: "memory")

// ---------------- Kernel 0: zero norm accumulators ----------------
__global__ void zero_kernel() {
    int i = blockIdx.x * 256 + threadIdx.x;
    if (i < B_ * 512) g_norm2[i] = 0.f;
}

// ---------------- Kernel 1: fused LayerNorm + transpose + bf16 split ----------------
__global__ __launch_bounds__(256) void lnconv_kernel(const float* __restrict__ x,
                                                     const float* __restrict__ gamma,
                                                     const float* __restrict__ beta) {
    __shared__ float s[256][33];
    __shared__ float p1[8][32], p2[8][32];
    __shared__ float mu_s[32], rs_s[32];
    int tid = threadIdx.x;
    int b = blockIdx.y, n0 = blockIdx.x * 32;
    int nl = tid & 31, g = tid >> 5;

    float a1 = 0.f, a2 = 0.f;
    for (int c = g; c < 256; c += 8) {
        float v = x[((size_t)b * 256 + c) * 4096 + n0 + nl];
        s[c][nl] = v;
        a1 += v; a2 += v * v;
    }
    p1[g][nl] = a1; p2[g][nl] = a2;
    __syncthreads();
    if (tid < 32) {
        float s1 = 0.f, s2 = 0.f;
        #pragma unroll
        for (int gg = 0; gg < 8; gg++) { s1 += p1[gg][tid]; s2 += p2[gg][tid]; }
        float mu = s1 * (1.0f / 256.0f);
        float var = s2 * (1.0f / 256.0f) - mu * mu;
        mu_s[tid] = mu;
        rs_s[tid] = rsqrtf(var + LN_EPS);
    }
    __syncthreads();

    float gm = gamma[tid], bt = beta[tid];
    #pragma unroll 4
    for (int n = 0; n < 32; n++) {
        float v = (s[tid][n] - mu_s[n]) * rs_s[n] * gm + bt;
        __nv_bfloat16 h = __float2bfloat16(v);
        __nv_bfloat16 l = __float2bfloat16(v - __bfloat162float(h));
        size_t o = ((size_t)b * 4096 + n0 + n) * 256 + tid;
        g_thi[o] = h;
        g_tlo[o] = l;
    }
}

// ---------------- Kernel 2: Wqkv transpose + split ----------------
__global__ void wsplit_kernel(const float* __restrict__ Wq) {
    __shared__ float tb[32][33];
    int bid = blockIdx.x;
    int m0 = (bid % 24) * 32, k0 = (bid / 24) * 32;
    int tx = threadIdx.x, ty = threadIdx.y;
    for (int r = ty; r < 32; r += 8)
        tb[r][tx] = Wq[(size_t)(k0 + r) * QKV3 + m0 + tx];
    __syncthreads();
    for (int r = ty; r < 32; r += 8) {
        float v = tb[tx][r];
        __nv_bfloat16 h = __float2bfloat16(v);
        __nv_bfloat16 l = __float2bfloat16(v - __bfloat162float(h));
        size_t o = (size_t)(m0 + r) * 256 + k0 + tx;
        g_wqh[o] = h; g_wql[o] = l;
    }
}

// ---------------- Kernel 3: QKV GEMM (R5-exact hot loop, specialized) ----------------
#define STG 32768

__global__ __launch_bounds__(256) void mgemm_kernel() {
    extern __shared__ char sm[];
    uint32_t smb = smem_u32(sm);

    int tid = threadIdx.x, wid = tid >> 5, lane = tid & 31;
    int qrow = lane >> 2, qcol = lane & 3;
    int warp_m = wid >> 2;
    int warp_n = wid & 3;
    int n0 = blockIdx.x * 128, j0 = blockIdx.y * 128, b = blockIdx.z;

    const uint4* Agh = (const uint4*)g_thi;
    const uint4* Agl = (const uint4*)g_tlo;
    const uint4* Bgh = (const uint4*)g_wqh;
    const uint4* Bgl = (const uint4*)g_wql;
    float* C = g_qkv;

    int lr0 = tid >> 2;
    int lc = tid & 3;
    uint32_t so0 = (uint32_t)(lr0 * 64 + ((lc ^ ((lr0 >> 1) & 3)) * 16));
    int lr1 = lr0 + 64;
    uint32_t so1 = (uint32_t)(lr1 * 64 + ((lc ^ ((lr1 >> 1) & 3)) * 16));

    float acc[4][4][4] = {};

    {
        size_t ga0 = ((size_t)(b * 4096 + n0 + lr0)) * 32 + lc;
        size_t ga1 = ((size_t)(b * 4096 + n0 + lr1)) * 32 + lc;
        size_t gb0 = ((size_t)(j0 + lr0)) * 32 + lc;
        size_t gb1 = ((size_t)(j0 + lr1)) * 32 + lc;
        cp16(smb + so0,         Agh + ga0);
        cp16(smb + so1,         Agh + ga1);
        cp16(smb + 8192 + so0,  Agl + ga0);
        cp16(smb + 8192 + so1,  Agl + ga1);
        cp16(smb + 16384 + so0, Bgh + gb0);
        cp16(smb + 16384 + so1, Bgh + gb1);
        cp16(smb + 24576 + so0, Bgl + gb0);
        cp16(smb + 24576 + so1, Bgl + gb1);
        CP_COMMIT();
    }

    int aRow = (lane & 15);
    int aCol = lane >> 4;
    int bRow = ((lane >> 4) << 3) + (lane & 7);
    int bCol = (lane >> 3) & 1;

    for (int chunk = 0; chunk < 8; chunk++) {
        if (chunk < 7) {
            int k8 = (chunk + 1) * 4;
            uint32_t st = smb + ((chunk + 1) & 1) * STG;
            size_t ga0 = ((size_t)(b * 4096 + n0 + lr0)) * 32 + k8 + lc;
            size_t ga1 = ((size_t)(b * 4096 + n0 + lr1)) * 32 + k8 + lc;
            size_t gb0 = ((size_t)(j0 + lr0)) * 32 + k8 + lc;
            size_t gb1 = ((size_t)(j0 + lr1)) * 32 + k8 + lc;
            cp16(st + so0,          Agh + ga0);
            cp16(st + so1,          Agh + ga1);
            cp16(st + 8192 + so0,   Agl + ga0);
            cp16(st + 8192 + so1,   Agl + ga1);
            cp16(st + 16384 + so0,  Bgh + gb0);
            cp16(st + 16384 + so1,  Bgh + gb1);
            cp16(st + 24576 + so0,  Bgl + gb0);
            cp16(st + 24576 + so1,  Bgl + gb1);
            CP_COMMIT();
            CP_WAIT1();
        } else {
            CP_WAIT0();
        }
        __syncthreads();

        uint32_t st = smb + (chunk & 1) * STG;
        #pragma unroll
        for (int kk = 0; kk < 2; kk++) {
            uint32_t bh[2][4], bl[2][4];
            #pragma unroll
            for (int np = 0; np < 2; np++) {
                int row = warp_n * 32 + np * 16 + bRow;
                uint32_t cc = (uint32_t)(((kk * 2) | bCol) ^ ((row >> 1) & 3));
                uint32_t ad = st + 16384 + (uint32_t)(row * 64) + cc * 16;
                ldsm4(bh[np], ad);
                ldsm4(bl[np], ad + 8192);
            }
            #pragma unroll
            for (int mf = 0; mf < 4; mf++) {
                int row = warp_m * 64 + mf * 16 + aRow;
                uint32_t cc = (uint32_t)(((kk * 2) | aCol) ^ ((row >> 1) & 3));
                uint32_t ad = st + (uint32_t)(row * 64) + cc * 16;
                uint32_t ah[4], al[4];
                ldsm4(ah, ad);
                ldsm4(al, ad + 8192);
                #pragma unroll
                for (int nf = 0; nf < 4; nf++) {
                    const uint32_t* bhf = &bh[nf >> 1][(nf & 1) * 2];
                    const uint32_t* blf = &bl[nf >> 1][(nf & 1) * 2];
                    mma_bf16(acc[mf][nf], ah, bhf);
                    mma_bf16(acc[mf][nf], ah, blf);
                    mma_bf16(acc[mf][nf], al, bhf);
                }
            }
        }
        __syncthreads();
    }

    #pragma unroll
    for (int mf = 0; mf < 4; mf++) {
        int m = n0 + warp_m * 64 + mf * 16 + qrow;
        #pragma unroll
        for (int nf = 0; nf < 4; nf++) {
            int j = j0 + warp_n * 32 + nf * 8 + qcol * 2;
            size_t r0 = ((size_t)b * QKV3 + j) * 4096 + m;
            size_t r1 = r0 + 4096;
            C[r0]     = acc[mf][nf][0];
            C[r1]     = acc[mf][nf][1];
            C[r0 + 8] = acc[mf][nf][2];
            C[r1 + 8] = acc[mf][nf][3];
        }
    }
}

// ---------------- Kernel 5: sim partials + fused q/k norm partials ----------------
#define CHN 128
#define PAD 132
__global__ void sim_part_kernel() {
    __shared__ float qs[32 * PAD];
    __shared__ float ks[32 * PAD];
    __shared__ float simbuf[32 * 32];

    int bh = blockIdx.x, z = blockIdx.y;
    int b = bh >> 3, h = bh & 7;
    int tid = threadIdx.x;
    const float* qbase = g_qkv + ((size_t)b * QKV3 + h * DH) * N_;
    const float* kbase = g_qkv + ((size_t)b * QKV3 + 256 + h * DH) * N_;

    for (int l = tid; l < 1024; l += 256) simbuf[l] = 0.f;

    int g = tid >> 6;
    int p = tid & 63;
    int ii0 = (p >> 3) * 4;
    int jj0 = (p & 7) * 4;
    float acc[4][4] = {};
    float qacc = 0.f, kacc = 0.f;

    int nrow = tid >> 3;
    int nseg = (tid & 7) * 16;

    int nstart = z * (N_ / ZSPLIT), nend = nstart + (N_ / ZSPLIT);
    for (int n0 = nstart; n0 < nend; n0 += CHN) {
        for (int e = tid * 4; e < 32 * CHN; e += 1024) {
            int row = e >> 7, t = e & (CHN - 1);
            *(float4*)&qs[row * PAD + t] = *(const float4*)&qbase[(size_t)row * N_ + n0 + t];
            *(float4*)&ks[row * PAD + t] = *(const float4*)&kbase[(size_t)row * N_ + n0 + t];
        }
        __syncthreads();

        {
            const float* qp = &qs[nrow * PAD + nseg];
            const float* kp = &ks[nrow * PAD + nseg];
            #pragma unroll
            for (int u = 0; u < 16; u += 4) {
                float4 a = *(const float4*)&qp[u];
                float4 c = *(const float4*)&kp[u];
                qacc += a.x * a.x + a.y * a.y + a.z * a.z + a.w * a.w;
                kacc += c.x * c.x + c.y * c.y + c.z * c.z + c.w * c.w;
            }
        }

        int tb = g * 32;
        #pragma unroll
        for (int s = 0; s < 8; s++) {
            int t = tb + s * 4;
            float4 qv[4], kv[4];
            #pragma unroll
            for (int r = 0; r < 4; r++) qv[r] = *(const float4*)&qs[(ii0 + r) * PAD + t];
            #pragma unroll
            for (int c = 0; c < 4; c++) kv[c] = *(const float4*)&ks[(jj0 + c) * PAD + t];
            #pragma unroll
            for (int r = 0; r < 4; r++)
                #pragma unroll
                for (int c = 0; c < 4; c++)
                    acc[r][c] += qv[r].x * kv[c].x + qv[r].y * kv[c].y
                               + qv[r].z * kv[c].z + qv[r].w * kv[c].w;
        }
        __syncthreads();
    }

    #pragma unroll
    for (int o = 4; o > 0; o >>= 1) {
        qacc += __shfl_down_sync(0xffffffffu, qacc, o);
        kacc += __shfl_down_sync(0xffffffffu, kacc, o);
    }
    if ((tid & 7) == 0) {
        atomicAdd(&g_norm2[b * 512 + h * DH + nrow], qacc);
        atomicAdd(&g_norm2[b * 512 + 256 + h * DH + nrow], kacc);
    }

    #pragma unroll
    for (int r = 0; r < 4; r++)
        #pragma unroll
        for (int c = 0; c < 4; c++)
            atomicAdd(&simbuf[(ii0 + r) * 32 + jj0 + c], acc[r][c]);
    __syncthreads();

    float* dst = g_simpart + ((size_t)(z * 128 + bh)) * 1024;
    for (int l = tid; l < 1024; l += 256) dst[l] = simbuf[l];
}

// ---------------- Kernel 6: reduce partials + scales + softmax -> attn ----------------
__global__ void softmax_kernel(const float* __restrict__ temp) {
    __shared__ float kinv[32];
    int bh = blockIdx.x;
    int i = threadIdx.x;
    int b = bh >> 3, h = bh & 7;

    float kn = g_norm2[b * 512 + 256 + h * DH + i];
    kinv[i] = 1.0f / fmaxf(sqrtf(kn), L2_EPS);
    float qn = g_norm2[b * 512 + h * DH + i];
    float qsc = expf(temp[h]) / fmaxf(sqrtf(qn), L2_EPS);
    __syncthreads();

    float row[32];
    float mx = -1e30f;
    #pragma unroll 4
    for (int j = 0; j < 32; j++) {
        float v = 0.f;
        #pragma unroll
        for (int z = 0; z < ZSPLIT; z++)
            v += g_simpart[((size_t)(z * 128 + bh)) * 1024 + i * 32 + j];
        v = v * qsc * kinv[j] * XC_SCALE;
        row[j] = v;
        mx = fmaxf(mx, v);
    }
    float sum = 0.f;
    #pragma unroll
    for (int j = 0; j < 32; j++) { row[j] = expf(row[j] - mx); sum += row[j]; }
    float inv = 1.0f / sum;
    #pragma unroll
    for (int j = 0; j < 32; j++)
        g_attn[((size_t)bh * 32 + i) * 32 + j] = row[j] * inv;
}

// ---------------- Kernel 7: M = Wout^T ∘ attn  (fp16 hi/lo, [b][o][c]) ----------------
__global__ __launch_bounds__(256) void mker_kernel(const float* __restrict__ Wout) {
    __shared__ float at[32][33];
    int b = blockIdx.x, h = blockIdx.y;
    int o = threadIdx.x;

    for (int l = o; l < 1024; l += 256)
        at[l >> 5][l & 31] = g_attn[((size_t)(b * 8 + h)) * 1024 + l];
    __syncthreads();

    float w[32];
    #pragma unroll 8
    for (int d = 0; d < 32; d++)
        w[d] = Wout[(size_t)(h * 32 + d) * 256 + o];

    size_t base = ((size_t)(b * 256 + o)) * 256 + h * 32;
    #pragma unroll 4
    for (int j = 0; j < 32; j++) {
        float s = 0.f;
        #pragma unroll
        for (int d = 0; d < 32; d++) s += w[d] * at[d][j];
        __half hi = __float2half_rn(s);
        __half lo = __float2half_rn(s - __half2float(hi));
        g_mhi[base + j] = hi;
        g_mlo[base + j] = lo;
    }
}

// ---------------- Kernel 8: vgemm  out[b][o][n] = M[b] @ v[b] + bias ----------------
#define VST_SSZ   16896                 // 32 rows x 132 floats
#define VST_A     (2 * VST_SSZ)        // 33792
#define VST_ASZ   8192
#define VST_BH    (VST_A + 2 * VST_ASZ)   // 50176
#define VST_BL    (VST_BH + 2 * 8192)     // 66560
#define VSMEM     (VST_BL + 2 * 8192)     // 82944

__global__ __launch_bounds__(256) void vgemm_kernel(float* __restrict__ out,
                                                    const float* __restrict__ bias) {
    extern __shared__ char sm[];
    uint32_t smb = smem_u32(sm);

    int tid = threadIdx.x, wid = tid >> 5, lane = tid & 31;
    int qrow = lane >> 2, qcol = lane & 3;
    int warp_m = wid >> 2;
    int warp_n = wid & 3;
    int n0 = blockIdx.x * 128, j0 = blockIdx.y * 128, b = blockIdx.z;

    const float* vsrc = g_qkv + ((size_t)(b * QKV3 + 512)) * N_;
    const uint4* Mh = (const uint4*)g_mhi;
    const uint4* Ml = (const uint4*)g_mlo;

    int sr = tid >> 5;
    int scol = tid & 31;
    int mr = tid >> 2;
    int mlc = tid & 3;
    uint32_t mso0 = (uint32_t)(mr * 64 + ((mlc ^ ((mr >> 1) & 3)) * 16));
    int mr1 = mr + 64;
    uint32_t mso1 = (uint32_t)(mr1 * 64 + ((mlc ^ ((mr1 >> 1) & 3)) * 16));
    size_t mg0 = ((size_t)(b * 256 + j0 + mr)) * 32 + mlc;
    size_t mg1 = ((size_t)(b * 256 + j0 + mr1)) * 32 + mlc;

    int tm = (wid & 3) * 32 + lane;
    int tch = (wid >> 2) * 16;
    int tg0 = tch >> 3;

    float acc[4][4][4] = {};

    {
        uint32_t stB = smb;
        #pragma unroll
        for (int r = 0; r < 4; r++) {
            int cr = r * 8 + sr;
            cp16(stB + (uint32_t)(cr * 528 + scol * 16),
                 vsrc + (size_t)cr * N_ + n0 + scol * 4);
        }
        cp16(smb + VST_BH + mso0, Mh + mg0);
        cp16(smb + VST_BH + mso1, Mh + mg1);
        cp16(smb + VST_BL + mso0, Ml + mg0);
        cp16(smb + VST_BL + mso1, Ml + mg1);
        CP_COMMIT();
    }

    int aRow = (lane & 15);
    int aCol = lane >> 4;
    int bRow = ((lane >> 4) << 3) + (lane & 7);
    int bCol = (lane >> 3) & 1;

    int cur = 0;
    for (int chunk = 0; chunk < 8; chunk++) {
        if (chunk < 7) {
            int nb = cur ^ 1;
            int c0 = (chunk + 1) * 32;
            uint32_t stB = smb + (uint32_t)nb * VST_SSZ;
            #pragma unroll
            for (int r = 0; r < 4; r++) {
                int cr = r * 8 + sr;
                cp16(stB + (uint32_t)(cr * 528 + scol * 16),
                     vsrc + (size_t)(c0 + cr) * N_ + n0 + scol * 4);
            }
            uint32_t bhB = smb + VST_BH + (uint32_t)nb * 8192;
            uint32_t blB = smb + VST_BL + (uint32_t)nb * 8192;
            cp16(bhB + mso0, Mh + mg0 + (chunk + 1) * 4);
            cp16(bhB + mso1, Mh + mg1 + (chunk + 1) * 4);
            cp16(blB + mso0, Ml + mg0 + (chunk + 1) * 4);
            cp16(blB + mso1, Ml + mg1 + (chunk + 1) * 4);
            CP_COMMIT();
            CP_WAIT1();
        } else {
            CP_WAIT0();
        }
        __syncthreads();

        // transpose staging[cur] (fp32 [c][n]) -> A[cur] (fp16 [m][c], swizzled)
        {
            const float* stg = (const float*)(sm + (size_t)cur * VST_SSZ);
            uint32_t u[8];
            #pragma unroll
            for (int i = 0; i < 8; i++) {
                float v0 = stg[(tch + 2 * i) * 132 + tm];
                float v1 = stg[(tch + 2 * i + 1) * 132 + tm];
                __half2 h2 = __floats2half2_rn(v0, v1);
                u[i] = *(uint32_t*)&h2;
            }
            uint32_t abase = smb + VST_A + (uint32_t)cur * VST_ASZ + (uint32_t)(tm * 64);
            uint32_t sw = (uint32_t)((tm >> 1) & 3);
            uint32_t a0 = abase + ((uint32_t)tg0 ^ sw) * 16;
            uint32_t a1 = abase + (((uint32_t)tg0 + 1) ^ sw) * 16;
            asm volatile("st.shared.v4.b32 [%0], {%1,%2,%3,%4};"
                         :: "r"(a0), "r"(u[0]), "r"(u[1]), "r"(u[2]), "r"(u[3]));
            asm volatile("st.shared.v4.b32 [%0], {%1,%2,%3,%4};"
                         :: "r"(a1), "r"(u[4]), "r"(u[5]), "r"(u[6]), "r"(u[7]));
        }
        __syncthreads();

        uint32_t ast = smb + VST_A + (uint32_t)cur * VST_ASZ;
        uint32_t bhst = smb + VST_BH + (uint32_t)cur * 8192;
        uint32_t blst = smb + VST_BL + (uint32_t)cur * 8192;
        #pragma unroll
        for (int kk = 0; kk < 2; kk++) {
            uint32_t bh[2][4], bl[2][4];
            #pragma unroll
            for (int np = 0; np < 2; np++) {
                int row = warp_n * 32 + np * 16 + bRow;
                uint32_t cc = (uint32_t)(((kk * 2) | bCol) ^ ((row >> 1) & 3));
                ldsm4(bh[np], bhst + (uint32_t)(row * 64) + cc * 16);
                ldsm4(bl[np], blst + (uint32_t)(row * 64) + cc * 16);
            }
            #pragma unroll
            for (int mf = 0; mf < 4; mf++) {
                int row = warp_m * 64 + mf * 16 + aRow;
                uint32_t cc = (uint32_t)(((kk * 2) | aCol) ^ ((row >> 1) & 3));
                uint32_t a[4];
                ldsm4(a, ast + (uint32_t)(row * 64) + cc * 16);
                #pragma unroll
                for (int nf = 0; nf < 4; nf++) {
                    const uint32_t* bhf = &bh[nf >> 1][(nf & 1) * 2];
                    const uint32_t* blf = &bl[nf >> 1][(nf & 1) * 2];
                    mma_f16(acc[mf][nf], a, bhf);
                    mma_f16(acc[mf][nf], a, blf);
                }
            }
        }
        __syncthreads();   // FIX: protect buffers [cur] from next chunk's cp.async writes
        cur ^= 1;
    }

    #pragma unroll
    for (int mf = 0; mf < 4; mf++) {
        int m = n0 + warp_m * 64 + mf * 16 + qrow;
        #pragma unroll
        for (int nf = 0; nf < 4; nf++) {
            int j = j0 + warp_n * 32 + nf * 8 + qcol * 2;
            float b0 = bias[j], b1 = bias[j + 1];
            size_t r0 = ((size_t)b * 256 + j) * 4096 + m;
            size_t r1 = r0 + 4096;
            out[r0]     = acc[mf][nf][0] + b0;
            out[r1]     = acc[mf][nf][1] + b1;
            out[r0 + 8] = acc[mf][nf][2] + b0;
            out[r1 + 8] = acc[mf][nf][3] + b1;
        }
    }
}

// ---------------- launch ----------------
extern "C" void kernel_launch(void* const* d_in, const int* in_sizes, int n_in,
                              void* d_out, int out_size) {
    const float* x     = (const float*)d_in[0];
    const float* gamma = (const float*)d_in[1];
    const float* beta  = (const float*)d_in[2];
    const float* Wqkv  = (const float*)d_in[3];
    const float* temp  = (const float*)d_in[4];
    const float* Wout  = (const float*)d_in[5];
    const float* bout  = (const float*)d_in[6];
    float* out = (float*)d_out;
    (void)in_sizes; (void)n_in; (void)out_size;

    cudaFuncSetAttribute(mgemm_kernel, cudaFuncAttributeMaxDynamicSharedMemorySize, 2 * STG);
    cudaFuncSetAttribute(vgemm_kernel, cudaFuncAttributeMaxDynamicSharedMemorySize, VSMEM);

    zero_kernel<<<32, 256>>>();
    lnconv_kernel<<<dim3(N_ / 32, B_), 256>>>(x, gamma, beta);
    wsplit_kernel<<<192, dim3(32, 8)>>>(Wqkv);
    // QKV projection
    mgemm_kernel<<<dim3(N_ / 128, QKV3 / 128, B_), 256, 2 * STG>>>();
    // sim partials (+norm partials), softmax
    sim_part_kernel<<<dim3(B_ * HEADS, ZSPLIT), 256>>>();
    softmax_kernel<<<B_ * HEADS, 32>>>(temp);
    // M = Wout^T ∘ attn
    mker_kernel<<<dim3(B_, HEADS), 256>>>(Wout);
    // out = M @ v + bias
    vgemm_kernel<<<dim3(N_ / 128, C_ / 128, B_), 256, VSMEM>>>(out, bout);
}

// round 14
// speedup vs baseline: 1.6449x; 1.6449x over previous
#include <cuda_runtime.h>
#include <cuda_bf16.h>
#include <cuda_fp16.h>
#include <math.h>
#include <stdint.h>

#define B_    16
#define C_    256
#define N_    4096
#define HEADS 8
#define DH    32
#define QKV3  768
#define LN_EPS 1e-5f
#define L2_EPS 1e-12f
#define XC_SCALE 8.0f
#define ZSPLIT 8

// ---------------- scratch ----------------
__device__ __nv_bfloat16 g_thi[(size_t)B_ * N_ * C_];
__device__ __nv_bfloat16 g_tlo[(size_t)B_ * N_ * C_];
__device__ float g_qkv[(size_t)B_ * QKV3 * N_];
__device__ float g_norm2[B_ * 512];
__device__ float g_simpart[ZSPLIT * B_ * HEADS * DH * DH];
__device__ float g_attn[B_ * HEADS * DH * DH];
__device__ __half g_mhi[(size_t)B_ * C_ * C_];            // M = Wout^T ∘ attn, [b][o][c]
__device__ __half g_mlo[(size_t)B_ * C_ * C_];
__device__ __nv_bfloat16 g_wqh[QKV3 * C_];
__device__ __nv_bfloat16 g_wql[QKV3 * C_];

__device__ __forceinline__ uint32_t smem_u32(const void* p) {
    uint32_t a;
    asm("{ .reg .u64 t; cvta.to.shared.u64 t, %1; cvt.u32.u64 %0, t; }" : "=r"(a) : "l"(p));
    return a;
}
__device__ __forceinline__ void mma_bf16(float* c, const uint32_t* a, const uint32_t* b) {
    asm volatile("mma.sync.aligned.m16n8k16.row.col.f32.bf16.bf16.f32 "
                 "{%0,%1,%2,%3}, {%4,%5,%6,%7}, {%8,%9}, {%0,%1,%2,%3};"
                 : "+f"(c[0]), "+f"(c[1]), "+f"(c[2]), "+f"(c[3])
                 : "r"(a[0]), "r"(a[1]), "r"(a[2]), "r"(a[3]), "r"(b[0]), "r"(b[1]));
}
__device__ __forceinline__ void mma_f16(float* c, const uint32_t* a, const uint32_t* b) {
    asm volatile("mma.sync.aligned.m16n8k16.row.col.f32.f16.f16.f32 "
                 "{%0,%1,%2,%3}, {%4,%5,%6,%7}, {%8,%9}, {%0,%1,%2,%3};"
                 : "+f"(c[0]), "+f"(c[1]), "+f"(c[2]), "+f"(c[3])
                 : "r"(a[0]), "r"(a[1]), "r"(a[2]), "r"(a[3]), "r"(b[0]), "r"(b[1]));
}
__device__ __forceinline__ void ldsm4(uint32_t* r, uint32_t addr) {
    asm volatile("ldmatrix.sync.aligned.m8n8.x4.shared.b16 {%0,%1,%2,%3}, [%4];"
                 : "=r"(r[0]), "=r"(r[1]), "=r"(r[2]), "=r"(r[3]) : "r"(addr));
}
__device__ __forceinline__ void cp16(uint32_t sa, const void* ga) {
    asm volatile("cp.async.cg.shared.global [%0], [%1], 16;" :: "r"(sa), "l"(ga) : "memory");
}
#define CP_COMMIT() asm volatile("cp.async.commit_group;" ::: "memory")
#define CP_WAIT1()  asm volatile("cp.async.wait_group 1;" ::: "memory")
#define CP_WAIT0()  asm volatile("cp.async.wait_group 0;" ::: "memory")

// ---------------- Kernel 0: zero norm accumulators ----------------
__global__ void zero_kernel() {
    int i = blockIdx.x * 256 + threadIdx.x;
    if (i < B_ * 512) g_norm2[i] = 0.f;
}

// ---------------- Kernel 1: fused LayerNorm + transpose + bf16 split ----------------
__global__ __launch_bounds__(256) void lnconv_kernel(const float* __restrict__ x,
                                                     const float* __restrict__ gamma,
                                                     const float* __restrict__ beta) {
    __shared__ float s[256][33];
    __shared__ float p1[8][32], p2[8][32];
    __shared__ float mu_s[32], rs_s[32];
    int tid = threadIdx.x;
    int b = blockIdx.y, n0 = blockIdx.x * 32;
    int nl = tid & 31, g = tid >> 5;

    float a1 = 0.f, a2 = 0.f;
    for (int c = g; c < 256; c += 8) {
        float v = x[((size_t)b * 256 + c) * 4096 + n0 + nl];
        s[c][nl] = v;
        a1 += v; a2 += v * v;
    }
    p1[g][nl] = a1; p2[g][nl] = a2;
    __syncthreads();
    if (tid < 32) {
        float s1 = 0.f, s2 = 0.f;
        #pragma unroll
        for (int gg = 0; gg < 8; gg++) { s1 += p1[gg][tid]; s2 += p2[gg][tid]; }
        float mu = s1 * (1.0f / 256.0f);
        float var = s2 * (1.0f / 256.0f) - mu * mu;
        mu_s[tid] = mu;
        rs_s[tid] = rsqrtf(var + LN_EPS);
    }
    __syncthreads();

    float gm = gamma[tid], bt = beta[tid];
    #pragma unroll 4
    for (int n = 0; n < 32; n++) {
        float v = (s[tid][n] - mu_s[n]) * rs_s[n] * gm + bt;
        __nv_bfloat16 h = __float2bfloat16(v);
        __nv_bfloat16 l = __float2bfloat16(v - __bfloat162float(h));
        size_t o = ((size_t)b * 4096 + n0 + n) * 256 + tid;
        g_thi[o] = h;
        g_tlo[o] = l;
    }
}

// ---------------- Kernel 2: Wqkv transpose + split ----------------
__global__ void wsplit_kernel(const float* __restrict__ Wq) {
    __shared__ float tb[32][33];
    int bid = blockIdx.x;
    int m0 = (bid % 24) * 32, k0 = (bid / 24) * 32;
    int tx = threadIdx.x, ty = threadIdx.y;
    for (int r = ty; r < 32; r += 8)
        tb[r][tx] = Wq[(size_t)(k0 + r) * QKV3 + m0 + tx];
    __syncthreads();
    for (int r = ty; r < 32; r += 8) {
        float v = tb[tx][r];
        __nv_bfloat16 h = __float2bfloat16(v);
        __nv_bfloat16 l = __float2bfloat16(v - __bfloat162float(h));
        size_t o = (size_t)(m0 + r) * 256 + k0 + tx;
        g_wqh[o] = h; g_wql[o] = l;
    }
}

// ---------------- Kernel 3: QKV GEMM (forced 2 CTAs/SM) ----------------
#define STG 32768

__global__ __launch_bounds__(256, 2) void mgemm_kernel() {
    extern __shared__ char sm[];
    uint32_t smb = smem_u32(sm);

    int tid = threadIdx.x, wid = tid >> 5, lane = tid & 31;
    int qrow = lane >> 2, qcol = lane & 3;
    int warp_m = wid >> 2;
    int warp_n = wid & 3;
    int n0 = blockIdx.x * 128, j0 = blockIdx.y * 128, b = blockIdx.z;

    const uint4* Agh = (const uint4*)g_thi;
    const uint4* Agl = (const uint4*)g_tlo;
    const uint4* Bgh = (const uint4*)g_wqh;
    const uint4* Bgl = (const uint4*)g_wql;
    float* C = g_qkv;

    int lr0 = tid >> 2;
    int lc = tid & 3;
    uint32_t so0 = (uint32_t)(lr0 * 64 + ((lc ^ ((lr0 >> 1) & 3)) * 16));
    int lr1 = lr0 + 64;
    uint32_t so1 = (uint32_t)(lr1 * 64 + ((lc ^ ((lr1 >> 1) & 3)) * 16));

    float acc[4][4][4] = {};

    {
        size_t ga0 = ((size_t)(b * 4096 + n0 + lr0)) * 32 + lc;
        size_t ga1 = ((size_t)(b * 4096 + n0 + lr1)) * 32 + lc;
        size_t gb0 = ((size_t)(j0 + lr0)) * 32 + lc;
        size_t gb1 = ((size_t)(j0 + lr1)) * 32 + lc;
        cp16(smb + so0,         Agh + ga0);
        cp16(smb + so1,         Agh + ga1);
        cp16(smb + 8192 + so0,  Agl + ga0);
        cp16(smb + 8192 + so1,  Agl + ga1);
        cp16(smb + 16384 + so0, Bgh + gb0);
        cp16(smb + 16384 + so1, Bgh + gb1);
        cp16(smb + 24576 + so0, Bgl + gb0);
        cp16(smb + 24576 + so1, Bgl + gb1);
        CP_COMMIT();
    }

    int aRow = (lane & 15);
    int aCol = lane >> 4;
    int bRow = ((lane >> 4) << 3) + (lane & 7);
    int bCol = (lane >> 3) & 1;

    for (int chunk = 0; chunk < 8; chunk++) {
        if (chunk < 7) {
            int k8 = (chunk + 1) * 4;
            uint32_t st = smb + ((chunk + 1) & 1) * STG;
            size_t ga0 = ((size_t)(b * 4096 + n0 + lr0)) * 32 + k8 + lc;
            size_t ga1 = ((size_t)(b * 4096 + n0 + lr1)) * 32 + k8 + lc;
            size_t gb0 = ((size_t)(j0 + lr0)) * 32 + k8 + lc;
            size_t gb1 = ((size_t)(j0 + lr1)) * 32 + k8 + lc;
            cp16(st + so0,          Agh + ga0);
            cp16(st + so1,          Agh + ga1);
            cp16(st + 8192 + so0,   Agl + ga0);
            cp16(st + 8192 + so1,   Agl + ga1);
            cp16(st + 16384 + so0,  Bgh + gb0);
            cp16(st + 16384 + so1,  Bgh + gb1);
            cp16(st + 24576 + so0,  Bgl + gb0);
            cp16(st + 24576 + so1,  Bgl + gb1);
            CP_COMMIT();
            CP_WAIT1();
        } else {
            CP_WAIT0();
        }
        __syncthreads();

        uint32_t st = smb + (chunk & 1) * STG;
        #pragma unroll
        for (int kk = 0; kk < 2; kk++) {
            uint32_t bh[2][4], bl[2][4];
            #pragma unroll
            for (int np = 0; np < 2; np++) {
                int row = warp_n * 32 + np * 16 + bRow;
                uint32_t cc = (uint32_t)(((kk * 2) | bCol) ^ ((row >> 1) & 3));
                uint32_t ad = st + 16384 + (uint32_t)(row * 64) + cc * 16;
                ldsm4(bh[np], ad);
                ldsm4(bl[np], ad + 8192);
            }
            #pragma unroll
            for (int mf = 0; mf < 4; mf++) {
                int row = warp_m * 64 + mf * 16 + aRow;
                uint32_t cc = (uint32_t)(((kk * 2) | aCol) ^ ((row >> 1) & 3));
                uint32_t ad = st + (uint32_t)(row * 64) + cc * 16;
                uint32_t ah[4], al[4];
                ldsm4(ah, ad);
                ldsm4(al, ad + 8192);
                #pragma unroll
                for (int nf = 0; nf < 4; nf++) {
                    const uint32_t* bhf = &bh[nf >> 1][(nf & 1) * 2];
                    const uint32_t* blf = &bl[nf >> 1][(nf & 1) * 2];
                    mma_bf16(acc[mf][nf], ah, bhf);
                    mma_bf16(acc[mf][nf], ah, blf);
                    mma_bf16(acc[mf][nf], al, bhf);
                }
            }
        }
        __syncthreads();
    }

    #pragma unroll
    for (int mf = 0; mf < 4; mf++) {
        int m = n0 + warp_m * 64 + mf * 16 + qrow;
        #pragma unroll
        for (int nf = 0; nf < 4; nf++) {
            int j = j0 + warp_n * 32 + nf * 8 + qcol * 2;
            size_t r0 = ((size_t)b * QKV3 + j) * 4096 + m;
            size_t r1 = r0 + 4096;
            C[r0]     = acc[mf][nf][0];
            C[r1]     = acc[mf][nf][1];
            C[r0 + 8] = acc[mf][nf][2];
            C[r1 + 8] = acc[mf][nf][3];
        }
    }
}

// ---------------- Kernel 5: sim partials + fused q/k norm partials ----------------
#define CHN 128
#define PAD 132
__global__ void sim_part_kernel() {
    __shared__ float qs[32 * PAD];
    __shared__ float ks[32 * PAD];
    __shared__ float simbuf[32 * 32];

    int bh = blockIdx.x, z = blockIdx.y;
    int b = bh >> 3, h = bh & 7;
    int tid = threadIdx.x;
    const float* qbase = g_qkv + ((size_t)b * QKV3 + h * DH) * N_;
    const float* kbase = g_qkv + ((size_t)b * QKV3 + 256 + h * DH) * N_;

    for (int l = tid; l < 1024; l += 256) simbuf[l] = 0.f;

    int g = tid >> 6;
    int p = tid & 63;
    int ii0 = (p >> 3) * 4;
    int jj0 = (p & 7) * 4;
    float acc[4][4] = {};
    float qacc = 0.f, kacc = 0.f;

    int nrow = tid >> 3;
    int nseg = (tid & 7) * 16;

    int nstart = z * (N_ / ZSPLIT), nend = nstart + (N_ / ZSPLIT);
    for (int n0 = nstart; n0 < nend; n0 += CHN) {
        for (int e = tid * 4; e < 32 * CHN; e += 1024) {
            int row = e >> 7, t = e & (CHN - 1);
            *(float4*)&qs[row * PAD + t] = *(const float4*)&qbase[(size_t)row * N_ + n0 + t];
            *(float4*)&ks[row * PAD + t] = *(const float4*)&kbase[(size_t)row * N_ + n0 + t];
        }
        __syncthreads();

        {
            const float* qp = &qs[nrow * PAD + nseg];
            const float* kp = &ks[nrow * PAD + nseg];
            #pragma unroll
            for (int u = 0; u < 16; u += 4) {
                float4 a = *(const float4*)&qp[u];
                float4 c = *(const float4*)&kp[u];
                qacc += a.x * a.x + a.y * a.y + a.z * a.z + a.w * a.w;
                kacc += c.x * c.x + c.y * c.y + c.z * c.z + c.w * c.w;
            }
        }

        int tb = g * 32;
        #pragma unroll
        for (int s = 0; s < 8; s++) {
            int t = tb + s * 4;
            float4 qv[4], kv[4];
            #pragma unroll
            for (int r = 0; r < 4; r++) qv[r] = *(const float4*)&qs[(ii0 + r) * PAD + t];
            #pragma unroll
            for (int c = 0; c < 4; c++) kv[c] = *(const float4*)&ks[(jj0 + c) * PAD + t];
            #pragma unroll
            for (int r = 0; r < 4; r++)
                #pragma unroll
                for (int c = 0; c < 4; c++)
                    acc[r][c] += qv[r].x * kv[c].x + qv[r].y * kv[c].y
                               + qv[r].z * kv[c].z + qv[r].w * kv[c].w;
        }
        __syncthreads();
    }

    #pragma unroll
    for (int o = 4; o > 0; o >>= 1) {
        qacc += __shfl_down_sync(0xffffffffu, qacc, o);
        kacc += __shfl_down_sync(0xffffffffu, kacc, o);
    }
    if ((tid & 7) == 0) {
        atomicAdd(&g_norm2[b * 512 + h * DH + nrow], qacc);
        atomicAdd(&g_norm2[b * 512 + 256 + h * DH + nrow], kacc);
    }

    #pragma unroll
    for (int r = 0; r < 4; r++)
        #pragma unroll
        for (int c = 0; c < 4; c++)
            atomicAdd(&simbuf[(ii0 + r) * 32 + jj0 + c], acc[r][c]);
    __syncthreads();

    float* dst = g_simpart + ((size_t)(z * 128 + bh)) * 1024;
    for (int l = tid; l < 1024; l += 256) dst[l] = simbuf[l];
}

// ---------------- Kernel 6: reduce partials + scales + softmax -> attn ----------------
__global__ void softmax_kernel(const float* __restrict__ temp) {
    __shared__ float kinv[32];
    int bh = blockIdx.x;
    int i = threadIdx.x;
    int b = bh >> 3, h = bh & 7;

    float kn = g_norm2[b * 512 + 256 + h * DH + i];
    kinv[i] = 1.0f / fmaxf(sqrtf(kn), L2_EPS);
    float qn = g_norm2[b * 512 + h * DH + i];
    float qsc = expf(temp[h]) / fmaxf(sqrtf(qn), L2_EPS);
    __syncthreads();

    float row[32];
    float mx = -1e30f;
    #pragma unroll 4
    for (int j = 0; j < 32; j++) {
        float v = 0.f;
        #pragma unroll
        for (int z = 0; z < ZSPLIT; z++)
            v += g_simpart[((size_t)(z * 128 + bh)) * 1024 + i * 32 + j];
        v = v * qsc * kinv[j] * XC_SCALE;
        row[j] = v;
        mx = fmaxf(mx, v);
    }
    float sum = 0.f;
    #pragma unroll
    for (int j = 0; j < 32; j++) { row[j] = expf(row[j] - mx); sum += row[j]; }
    float inv = 1.0f / sum;
    #pragma unroll
    for (int j = 0; j < 32; j++)
        g_attn[((size_t)bh * 32 + i) * 32 + j] = row[j] * inv;
}

// ---------------- Kernel 7: M = Wout^T ∘ attn  (fp16 hi/lo, [b][o][c]) ----------------
__global__ __launch_bounds__(256) void mker_kernel(const float* __restrict__ Wout) {
    __shared__ float at[32][33];
    int b = blockIdx.x, h = blockIdx.y;
    int o = threadIdx.x;

    for (int l = o; l < 1024; l += 256)
        at[l >> 5][l & 31] = g_attn[((size_t)(b * 8 + h)) * 1024 + l];
    __syncthreads();

    float w[32];
    #pragma unroll 8
    for (int d = 0; d < 32; d++)
        w[d] = Wout[(size_t)(h * 32 + d) * 256 + o];

    size_t base = ((size_t)(b * 256 + o)) * 256 + h * 32;
    #pragma unroll 4
    for (int j = 0; j < 32; j++) {
        float s = 0.f;
        #pragma unroll
        for (int d = 0; d < 32; d++) s += w[d] * at[d][j];
        __half hi = __float2half_rn(s);
        __half lo = __float2half_rn(s - __half2float(hi));
        g_mhi[base + j] = hi;
        g_mlo[base + j] = lo;
    }
}

// ---------------- Kernel 8: vgemm  out[b][o][n] = M[b] @ v[b] + bias ----------------
#define VST_SSZ   16896                 // 32 rows x 132 floats
#define VST_A     (2 * VST_SSZ)        // 33792
#define VST_ASZ   8192
#define VST_BH    (VST_A + 2 * VST_ASZ)   // 50176
#define VST_BL    (VST_BH + 2 * 8192)     // 66560
#define VSMEM     (VST_BL + 2 * 8192)     // 82944

__global__ __launch_bounds__(256, 2) void vgemm_kernel(float* __restrict__ out,
                                                       const float* __restrict__ bias) {
    extern __shared__ char sm[];
    uint32_t smb = smem_u32(sm);

    int tid = threadIdx.x, wid = tid >> 5, lane = tid & 31;
    int qrow = lane >> 2, qcol = lane & 3;
    int warp_m = wid >> 2;
    int warp_n = wid & 3;
    int n0 = blockIdx.x * 128, j0 = blockIdx.y * 128, b = blockIdx.z;

    const float* vsrc = g_qkv + ((size_t)(b * QKV3 + 512)) * N_;
    const uint4* Mh = (const uint4*)g_mhi;
    const uint4* Ml = (const uint4*)g_mlo;

    int sr = tid >> 5;
    int scol = tid & 31;
    int mr = tid >> 2;
    int mlc = tid & 3;
    uint32_t mso0 = (uint32_t)(mr * 64 + ((mlc ^ ((mr >> 1) & 3)) * 16));
    int mr1 = mr + 64;
    uint32_t mso1 = (uint32_t)(mr1 * 64 + ((mlc ^ ((mr1 >> 1) & 3)) * 16));
    size_t mg0 = ((size_t)(b * 256 + j0 + mr)) * 32 + mlc;
    size_t mg1 = ((size_t)(b * 256 + j0 + mr1)) * 32 + mlc;

    int tm = (wid & 3) * 32 + lane;
    int tch = (wid >> 2) * 16;
    int tg0 = tch >> 3;

    float acc[4][4][4] = {};

    {
        uint32_t stB = smb;
        #pragma unroll
        for (int r = 0; r < 4; r++) {
            int cr = r * 8 + sr;
            cp16(stB + (uint32_t)(cr * 528 + scol * 16),
                 vsrc + (size_t)cr * N_ + n0 + scol * 4);
        }
        cp16(smb + VST_BH + mso0, Mh + mg0);
        cp16(smb + VST_BH + mso1, Mh + mg1);
        cp16(smb + VST_BL + mso0, Ml + mg0);
        cp16(smb + VST_BL + mso1, Ml + mg1);
        CP_COMMIT();
    }

    int aRow = (lane & 15);
    int aCol = lane >> 4;
    int bRow = ((lane >> 4) << 3) + (lane & 7);
    int bCol = (lane >> 3) & 1;

    int cur = 0;
    for (int chunk = 0; chunk < 8; chunk++) {
        if (chunk < 7) {
            int nb = cur ^ 1;
            int c0 = (chunk + 1) * 32;
            uint32_t stB = smb + (uint32_t)nb * VST_SSZ;
            #pragma unroll
            for (int r = 0; r < 4; r++) {
                int cr = r * 8 + sr;
                cp16(stB + (uint32_t)(cr * 528 + scol * 16),
                     vsrc + (size_t)(c0 + cr) * N_ + n0 + scol * 4);
            }
            uint32_t bhB = smb + VST_BH + (uint32_t)nb * 8192;
            uint32_t blB = smb + VST_BL + (uint32_t)nb * 8192;
            cp16(bhB + mso0, Mh + mg0 + (chunk + 1) * 4);
            cp16(bhB + mso1, Mh + mg1 + (chunk + 1) * 4);
            cp16(blB + mso0, Ml + mg0 + (chunk + 1) * 4);
            cp16(blB + mso1, Ml + mg1 + (chunk + 1) * 4);
            CP_COMMIT();
            CP_WAIT1();
        } else {
            CP_WAIT0();
        }
        __syncthreads();

        // transpose staging[cur] (fp32 [c][n]) -> A[cur] (fp16 [m][c], swizzled)
        {
            const float* stg = (const float*)(sm + (size_t)cur * VST_SSZ);
            uint32_t u[8];
            #pragma unroll
            for (int i = 0; i < 8; i++) {
                float v0 = stg[(tch + 2 * i) * 132 + tm];
                float v1 = stg[(tch + 2 * i + 1) * 132 + tm];
                __half2 h2 = __floats2half2_rn(v0, v1);
                u[i] = *(uint32_t*)&h2;
            }
            uint32_t abase = smb + VST_A + (uint32_t)cur * VST_ASZ + (uint32_t)(tm * 64);
            uint32_t sw = (uint32_t)((tm >> 1) & 3);
            uint32_t a0 = abase + ((uint32_t)tg0 ^ sw) * 16;
            uint32_t a1 = abase + (((uint32_t)tg0 + 1) ^ sw) * 16;
            asm volatile("st.shared.v4.b32 [%0], {%1,%2,%3,%4};"
                         :: "r"(a0), "r"(u[0]), "r"(u[1]), "r"(u[2]), "r"(u[3]));
            asm volatile("st.shared.v4.b32 [%0], {%1,%2,%3,%4};"
                         :: "r"(a1), "r"(u[4]), "r"(u[5]), "r"(u[6]), "r"(u[7]));
        }
        __syncthreads();

        uint32_t ast = smb + VST_A + (uint32_t)cur * VST_ASZ;
        uint32_t bhst = smb + VST_BH + (uint32_t)cur * 8192;
        uint32_t blst = smb + VST_BL + (uint32_t)cur * 8192;
        #pragma unroll
        for (int kk = 0; kk < 2; kk++) {
            uint32_t bh[2][4], bl[2][4];
            #pragma unroll
            for (int np = 0; np < 2; np++) {
                int row = warp_n * 32 + np * 16 + bRow;
                uint32_t cc = (uint32_t)(((kk * 2) | bCol) ^ ((row >> 1) & 3));
                ldsm4(bh[np], bhst + (uint32_t)(row * 64) + cc * 16);
                ldsm4(bl[np], blst + (uint32_t)(row * 64) + cc * 16);
            }
            #pragma unroll
            for (int mf = 0; mf < 4; mf++) {
                int row = warp_m * 64 + mf * 16 + aRow;
                uint32_t cc = (uint32_t)(((kk * 2) | aCol) ^ ((row >> 1) & 3));
                uint32_t a[4];
                ldsm4(a, ast + (uint32_t)(row * 64) + cc * 16);
                #pragma unroll
                for (int nf = 0; nf < 4; nf++) {
                    const uint32_t* bhf = &bh[nf >> 1][(nf & 1) * 2];
                    const uint32_t* blf = &bl[nf >> 1][(nf & 1) * 2];
                    mma_f16(acc[mf][nf], a, bhf);
                    mma_f16(acc[mf][nf], a, blf);
                }
            }
        }
        __syncthreads();
        cur ^= 1;
    }

    #pragma unroll
    for (int mf = 0; mf < 4; mf++) {
        int m = n0 + warp_m * 64 + mf * 16 + qrow;
        #pragma unroll
        for (int nf = 0; nf < 4; nf++) {
            int j = j0 + warp_n * 32 + nf * 8 + qcol * 2;
            float b0 = bias[j], b1 = bias[j + 1];
            size_t r0 = ((size_t)b * 256 + j) * 4096 + m;
            size_t r1 = r0 + 4096;
            out[r0]     = acc[mf][nf][0] + b0;
            out[r1]     = acc[mf][nf][1] + b1;
            out[r0 + 8] = acc[mf][nf][2] + b0;
            out[r1 + 8] = acc[mf][nf][3] + b1;
        }
    }
}

// ---------------- launch ----------------
extern "C" void kernel_launch(void* const* d_in, const int* in_sizes, int n_in,
                              void* d_out, int out_size) {
    const float* x     = (const float*)d_in[0];
    const float* gamma = (const float*)d_in[1];
    const float* beta  = (const float*)d_in[2];
    const float* Wqkv  = (const float*)d_in[3];
    const float* temp  = (const float*)d_in[4];
    const float* Wout  = (const float*)d_in[5];
    const float* bout  = (const float*)d_in[6];
    float* out = (float*)d_out;
    (void)in_sizes; (void)n_in; (void)out_size;

    cudaFuncSetAttribute(mgemm_kernel, cudaFuncAttributeMaxDynamicSharedMemorySize, 2 * STG);
    cudaFuncSetAttribute(vgemm_kernel, cudaFuncAttributeMaxDynamicSharedMemorySize, VSMEM);

    zero_kernel<<<32, 256>>>();
    lnconv_kernel<<<dim3(N_ / 32, B_), 256>>>(x, gamma, beta);
    wsplit_kernel<<<192, dim3(32, 8)>>>(Wqkv);
    // QKV projection
    mgemm_kernel<<<dim3(N_ / 128, QKV3 / 128, B_), 256, 2 * STG>>>();
    // sim partials (+norm partials), softmax
    sim_part_kernel<<<dim3(B_ * HEADS, ZSPLIT), 256>>>();
    softmax_kernel<<<B_ * HEADS, 32>>>(temp);
    // M = Wout^T ∘ attn
    mker_kernel<<<dim3(B_, HEADS), 256>>>(Wout);
    // out = M @ v + bias
    vgemm_kernel<<<dim3(N_ / 128, C_ / 128, B_), 256, VSMEM>>>(out, bout);
}